// round 3
// baseline (speedup 1.0000x reference)
#include <cuda_runtime.h>
#include <math.h>

#define TT 1024
#define BB 16
#define SS 2
#define NN 2048
#define BN (BB * NN)     // 32768
#define LL 100

// Bit-exact replication of the reference fp32 arithmetic.
//
// EPSP: x in {0,1} -> conv sum == fold of kernel taps at spike lags, in the
//       reference's accumulation order (oldest lag first), per synapse, then
//       v = v0 + v1. Adding the zero terms is an exact no-op in fp32, so
//       skipping them is bit-exact.
// Refractory: the slot read as buf[0] at time t accumulated, in time order,
//       round(nadj_te * (-refk[t-te])) for te = t-99..t-1. Zero spikes add
//       exact +/-0.0 (identity on non-positive partials) -> skip. We keep a
//       compressed FIFO of (te, nadj) and fold oldest-first with separate
//       FMUL + FADD (NO fma) to match the reference's rounding.
// Straight-through: nadj = (n - sg*v) + sg*v with sg = 2*expf(-2|v-1|);
//       expf lowers to libdevice __nv_expf (same as XLA GPU).
__global__ __launch_bounds__(64) void snn_exact_kernel(
    const float* __restrict__ spikes,   // (T, B, S, N)
    const float* __restrict__ eps,      // (S, L) = (2, 100)
    const float* __restrict__ refk,     // (L,)
    float* __restrict__ out)            // (T, B, N)
{
    __shared__ float sk0[LL], sk1[LL], sr[LL];
    for (int i = threadIdx.x; i < LL; i += 64) {
        sk0[i] = eps[i];
        sk1[i] = eps[LL + i];
        sr[i]  = refk[i];
    }
    __syncthreads();

    const int bn = blockIdx.x * 64 + threadIdx.x;
    const int b = bn >> 11;            // / NN
    const int n = bn & (NN - 1);

    // spike-history bitmasks, bit l == spike at lag l (l = t - t_spike)
    unsigned m0a = 0u, m0b = 0u, m0c = 0u, m0d = 0u;
    unsigned m1a = 0u, m1b = 0u, m1c = 0u, m1d = 0u;

    // refractory FIFO: packed (te as int bits, nadj) in float2 -> LDL.64
    float2 fifo[128];
    int head = 0, tail = 0;

    const float* p0 = spikes + (size_t)b * SS * NN + n;   // syn 0
    const float* p1 = p0 + NN;                            // syn 1
    float* po = out + (size_t)b * NN + n;
    const int strideIn = BB * SS * NN;                    // 65536

    for (int t = 0; t < TT; ++t) {
        const unsigned x0 = (__ldg(p0 + (size_t)t * strideIn) != 0.0f) ? 1u : 0u;
        const unsigned x1 = (__ldg(p1 + (size_t)t * strideIn) != 0.0f) ? 1u : 0u;

        // shift lag masks by 1, insert new bit at lag 0, keep lags 0..99
        m0d = ((m0d << 1) | (m0c >> 31)) & 0xFu;
        m0c = (m0c << 1) | (m0b >> 31);
        m0b = (m0b << 1) | (m0a >> 31);
        m0a = (m0a << 1) | x0;
        m1d = ((m1d << 1) | (m1c >> 31)) & 0xFu;
        m1c = (m1c << 1) | (m1b >> 31);
        m1b = (m1b << 1) | (m1a >> 31);
        m1a = (m1a << 1) | x1;

        // EPSP fold, oldest lag (highest l) first, per synapse
        float a0 = 0.0f, a1 = 0.0f;
        {
            unsigned w[4] = {m0a, m0b, m0c, m0d};
#pragma unroll
            for (int wi = 3; wi >= 0; --wi) {
                unsigned mm = w[wi];
                while (mm) {
                    const int bp = 31 - __clz(mm);
                    mm &= ~(1u << bp);
                    a0 = __fadd_rn(a0, sk0[wi * 32 + bp]);
                }
            }
        }
        {
            unsigned w[4] = {m1a, m1b, m1c, m1d};
#pragma unroll
            for (int wi = 3; wi >= 0; --wi) {
                unsigned mm = w[wi];
                while (mm) {
                    const int bp = 31 - __clz(mm);
                    mm &= ~(1u << bp);
                    a1 = __fadd_rn(a1, sk1[wi * 32 + bp]);
                }
            }
        }
        const float v = __fadd_rn(a0, a1);   // vmem_syn.sum(axis=1)

        // expire refractory entries with lag >= 100 (at most one per step)
        if (head != tail) {
            if (__float_as_int(fifo[head & 127].x) <= t - LL) ++head;
        }

        // buf[0]: fold oldest-first, mul-then-add rounding
        float racc = 0.0f;
        for (int i = head; i != tail; ++i) {
            const float2 e = fifo[i & 127];
            const int d = t - __float_as_int(e.x);
            const float p = __fmul_rn(e.y, sr[d]);  // round(nadj * refk[d])
            racc = __fsub_rn(racc, p);              // == racc + round(nadj * (-refk[d]))
        }

        const float veff = __fadd_rn(v, racc);      // v_t + buf[0]
        const float nsp = floorf(fmaxf(veff, 0.0f));

        // straight-through value: (n - sg*v) + sg*v
        const float ad = fabsf(__fsub_rn(veff, 1.0f));
        const float sg = __fmul_rn(2.0f, expf(__fmul_rn(ad, -2.0f)));
        const float term = __fmul_rn(sg, veff);
        const float nadj = __fadd_rn(__fsub_rn(nsp, term), term);

        if (nadj != 0.0f) {
            float2 e;
            e.x = __int_as_float(t);
            e.y = nadj;
            fifo[tail & 127] = e;
            ++tail;
        }

        po[(size_t)t * BN] = nadj;
    }
}

extern "C" void kernel_launch(void* const* d_in, const int* in_sizes, int n_in,
                              void* d_out, int out_size) {
    const float* spikes = (const float*)d_in[0];   // (T,B,S,N) float32
    const float* eps    = (const float*)d_in[1];   // (2,100)   float32
    const float* refk   = (const float*)d_in[2];   // (100,)    float32
    float* out = (float*)d_out;                    // (T,B,N)   float32
    snn_exact_kernel<<<BN / 64, 64>>>(spikes, eps, refk, out);
}

// round 5
// speedup vs baseline: 1.8471x; 1.8471x over previous
#include <cuda_runtime.h>
#include <math.h>

#define TT 1024
#define BB 16
#define SS 2
#define NN 2048
#define BN (BB * NN)     // 32768
#define LL 100

// Scratch: vmem laid out (bn, t) -> phase1 writes coalesced (lanes = consecutive t),
// phase2 reads hit the same 128B line for 32 consecutive steps (L1-resident).
__device__ float g_vmem[(size_t)BN * TT];

// ---------------------------------------------------------------------------
// Phase 1: EPSP conv, bit-exact fold (oldest spike time first, per synapse,
// then v = a0 + a1), parallel over (bn, t).
// Block = 256 threads handles 32 consecutive neurons (same b) x all T.
// ---------------------------------------------------------------------------
__global__ __launch_bounds__(256) void snn_epsp_kernel(
    const float* __restrict__ spikes,   // (T, B, S, N)
    const float* __restrict__ eps)      // (S, L)
{
    __shared__ unsigned smasks[2 * TT];       // [s*TT + t], bit i = neuron n0+i
    __shared__ unsigned sW[2 * 32 * 32];      // [s*1024 + j*32 + w], bit i = t = w*32+i
    __shared__ float sk[2 * LL];

    const int tid = threadIdx.x;
    const int warpId = tid >> 5;
    const int lane = tid & 31;
    const int b  = blockIdx.x >> 6;           // N/32 = 64 blocks per batch
    const int n0 = (blockIdx.x & 63) * 32;

    for (int i = tid; i < 2 * LL; i += 256) sk[i] = eps[i];

    // ballot spikes -> per-(s,t) neuron masks
    for (int idx = warpId; idx < 2 * TT; idx += 8) {
        const int s = idx >> 10;
        const int t = idx & (TT - 1);
        const float val = spikes[(((size_t)t * BB + b) * SS + s) * NN + n0 + lane];
        const unsigned m = __ballot_sync(0xFFFFFFFFu, val != 0.0f);
        if (lane == 0) smasks[s * TT + t] = m;
    }
    __syncthreads();

    // bit-transpose: per-neuron time-words
    {
        const int j = tid & 31;
        const int wbase = tid >> 5;   // 0..7
#pragma unroll
        for (int s = 0; s < 2; ++s) {
#pragma unroll
            for (int k = 0; k < 4; ++k) {
                const int w = wbase + 8 * k;
                unsigned acc = 0;
                const unsigned* mp = &smasks[s * TT + w * 32];
#pragma unroll
                for (int i = 0; i < 32; ++i)
                    acc |= ((mp[i] >> j) & 1u) << i;
                sW[s * 1024 + j * 32 + w] = acc;
            }
        }
    }
    __syncthreads();

    // conv: warp -> neuron j, lanes -> consecutive t (divergence-free bit walks)
#pragma unroll 1
    for (int jj = 0; jj < 4; ++jj) {
        const int j = warpId + jj * 8;
        const size_t obase = ((size_t)(b * NN + n0 + j)) * TT;
        const unsigned* W0 = &sW[j * 32];
        const unsigned* W1 = &sW[1024 + j * 32];
#pragma unroll 1
        for (int chunk = 0; chunk < 32; ++chunk) {
            const int t = chunk * 32 + lane;
            const int tlo = (t >= LL - 1) ? t - (LL - 1) : 0;
            const int wlo = tlo >> 5, whi = t >> 5;
            const unsigned mlo = 0xFFFFFFFFu << (tlo & 31);
            const int r = t & 31;
            const unsigned mhi = (r == 31) ? 0xFFFFFFFFu : ((2u << r) - 1u);

            float a0 = 0.0f;
            for (int w = wlo; w <= whi; ++w) {
                unsigned mm = W0[w];
                if (w == wlo) mm &= mlo;
                if (w == whi) mm &= mhi;
                const int base = w << 5;
                while (mm) {
                    const int i = __ffs(mm) - 1;
                    mm &= mm - 1;
                    a0 = __fadd_rn(a0, sk[t - (base + i)]);
                }
            }
            float a1 = 0.0f;
            for (int w = wlo; w <= whi; ++w) {
                unsigned mm = W1[w];
                if (w == wlo) mm &= mlo;
                if (w == whi) mm &= mhi;
                const int base = w << 5;
                while (mm) {
                    const int i = __ffs(mm) - 1;
                    mm &= mm - 1;
                    a1 = __fadd_rn(a1, sk[LL + t - (base + i)]);
                }
            }
            g_vmem[obase + t] = __fadd_rn(a0, a1);
        }
    }
}

// ---------------------------------------------------------------------------
// Phase 2: sequential threshold + refractory scan. Numerics identical to the
// R3 passing kernel (FIFO fold oldest-first, mul-then-add, expf, straight-
// through perturbation).
// ---------------------------------------------------------------------------
__global__ __launch_bounds__(128) void snn_scan_kernel(
    const float* __restrict__ refk,     // (L,)
    float* __restrict__ out)            // (T, B, N)
{
    __shared__ float sr[LL];
    for (int i = threadIdx.x; i < LL; i += 128) sr[i] = refk[i];
    __syncthreads();

    const int bn = blockIdx.x * 128 + threadIdx.x;
    const float* pv = g_vmem + (size_t)bn * TT;
    float* po = out + bn;

    float fV[LL];               // spike values
    unsigned short fT[LL];      // spike times
    int hpos = 0, tpos = 0, cnt = 0;

#pragma unroll 1
    for (int t = 0; t < TT; ++t) {
        const float v = pv[t];

        // expire (at most one entry per step can cross d >= 100)
        if (cnt && (int)fT[hpos] <= t - LL) {
            ++hpos; if (hpos == LL) hpos = 0;
            --cnt;
        }

        // buf[0]: fold oldest-first, mul-then-add rounding
        float racc = 0.0f;
        int i = hpos;
        for (int e = 0; e < cnt; ++e) {
            const int d = t - (int)fT[i];
            racc = __fsub_rn(racc, __fmul_rn(fV[i], sr[d]));
            ++i; if (i == LL) i = 0;
        }

        const float veff = __fadd_rn(v, racc);
        const float nsp = floorf(fmaxf(veff, 0.0f));

        const float ad = fabsf(__fsub_rn(veff, 1.0f));
        const float sg = __fmul_rn(2.0f, expf(__fmul_rn(ad, -2.0f)));
        const float term = __fmul_rn(sg, veff);
        const float nadj = __fadd_rn(__fsub_rn(nsp, term), term);

        if (nadj != 0.0f) {
            fV[tpos] = nadj;
            fT[tpos] = (unsigned short)t;
            ++tpos; if (tpos == LL) tpos = 0;
            ++cnt;
        }

        po[(size_t)t * BN] = nadj;
    }
}

extern "C" void kernel_launch(void* const* d_in, const int* in_sizes, int n_in,
                              void* d_out, int out_size) {
    const float* spikes = (const float*)d_in[0];   // (T,B,S,N) float32
    const float* eps    = (const float*)d_in[1];   // (2,100)   float32
    const float* refk   = (const float*)d_in[2];   // (100,)    float32
    float* out = (float*)d_out;                    // (T,B,N)   float32

    snn_epsp_kernel<<<BN / 32, 256>>>(spikes, eps);
    snn_scan_kernel<<<BN / 128, 128>>>(refk, out);
}